// round 12
// baseline (speedup 1.0000x reference)
#include <cuda_runtime.h>
#include <cstdint>

// CRF Viterbi decode: B=128, T=1024, K=128. One CTA (128 threads) per batch.
// Forward (R6-proven): thread per column j; 32x broadcast LDS.128 of state,
// 64x add.rn.f32x2 vs transitions in 64 u64 regs, 8-acc FMNMX tree; post-
// logit state history -> 64MB scratch (one STG/step); logits cp.async
// double-buffered; one __syncthreads per step.
// Backtrack (R12): warp 0 walks reading state rows DIRECTLY from gmem
// (coalesced float4/lane, 2-row register prefetch, L2-resident) — no smem
// staging, no barriers in the walk. Argmax chain = local IMNMX tree +
// ONE __reduce_max_sync + ballot + ffs + shfl (exact first-index tie-break
// matching jnp.argmax). One-hot f32 out, coalesced float4 stores.

#define BB 128
#define TT 1024
#define KK 128
#define TC_STRIDE 132
#define NTHREADS 128

__device__ float g_state[(size_t)BB * TT * KK];

struct __align__(16) SmemLayout {
    float transC[KK * TC_STRIDE];   // transC[j*132 + i] = T[i][j]
    float spad[2][KK];              // double-buffered state
    float logit[2][16][KK];         // double-buffered logit staging
    int   tags[TT];
    int   lasttag;
};

__device__ __forceinline__ unsigned smem_u32(const void* p) {
    return (unsigned)__cvta_generic_to_shared(p);
}
__device__ __forceinline__ void cp_async16(unsigned dst, const void* src) {
    asm volatile("cp.async.cg.shared.global [%0], [%1], 16;" :: "r"(dst), "l"(src));
}
__device__ __forceinline__ unsigned f32_mono_u32(float x) {
    unsigned b = __float_as_uint(x);
    return b ^ (unsigned)(((int)b >> 31) | 0x80000000);
}

__global__ void __launch_bounds__(NTHREADS, 1)
crf_viterbi_kernel(const float* __restrict__ logits,
                   const int*   __restrict__ lens,
                   const float* __restrict__ trans,
                   float*       __restrict__ out)
{
    extern __shared__ char smraw[];
    SmemLayout& s = *reinterpret_cast<SmemLayout*>(smraw);

    const int b    = blockIdx.x;
    const int tid  = threadIdx.x;
    const int w    = tid >> 5;         // 4 warps
    const int lane = tid & 31;
    const int j    = tid;              // output column owned by this thread
    const int len  = lens[b];

    // ---- transC staging (vectorized read, strided scalar STS; init-only) ----
    for (int idx = tid * 4; idx < KK * KK; idx += NTHREADS * 4) {
        float4 v = *reinterpret_cast<const float4*>(trans + idx);
        int i  = idx >> 7;
        int jj = idx & (KK - 1);
        s.transC[(jj + 0) * TC_STRIDE + i] = v.x;
        s.transC[(jj + 1) * TC_STRIDE + i] = v.y;
        s.transC[(jj + 2) * TC_STRIDE + i] = v.z;
        s.transC[(jj + 3) * TC_STRIDE + i] = v.w;
    }

    // ---- init state = logits[b, 0, :] ----
    {
        float v = logits[((size_t)b * TT) * KK + tid];
        s.spad[0][tid] = v;
        g_state[((size_t)b * TT) * KK + tid] = v;
    }

    // ---- prologue: stage logit rows 1..16 into buffer 0 ----
    {
        const float* base = logits + (size_t)b * TT * KK + lane * 4;
        #pragma unroll
        for (int k = 0; k < 4; ++k) {
            int ridx = w + 4 * k;          // row-in-epoch 0..15
            int r = 1 + ridx;  if (r > TT - 1) r = TT - 1;
            cp_async16(smem_u32(&s.logit[0][ridx][lane * 4]), base + (size_t)r * KK);
        }
        asm volatile("cp.async.commit_group;");
    }
    __syncthreads();

    // ---- this thread's 128 transitions (column j) from SMEM, 64 f32x2 ----
    unsigned long long t2[64];
    #pragma unroll
    for (int m = 0; m < 64; ++m) {
        float2 tp = *reinterpret_cast<const float2*>(
            &s.transC[j * TC_STRIDE + 2 * m]);
        asm("mov.b64 %0, {%1, %2};" : "=l"(t2[m]) : "f"(tp.x), "f"(tp.y));
    }

    const unsigned sb0 = smem_u32(&s.spad[0][0]);
    const unsigned sb1 = smem_u32(&s.spad[1][0]);
    int pr = 0;

    // ================= forward pass (value-only) =================
    for (int t = 1; t < len; ++t) {
        const int rel = t - 1;
        if ((rel & 15) == 0) {
            int g = rel >> 4;
            int base_row = 1 + (g + 1) * 16;
            int nb = (g + 1) & 1;
            const float* base = logits + (size_t)b * TT * KK + lane * 4;
            #pragma unroll
            for (int k = 0; k < 4; ++k) {
                int ridx = w + 4 * k;
                int r = base_row + ridx;  if (r > TT - 1) r = TT - 1;
                cp_async16(smem_u32(&s.logit[nb][ridx][lane * 4]),
                           base + (size_t)r * KK);
            }
            asm volatile("cp.async.commit_group;");
            asm volatile("cp.async.wait_group 1;");
            __syncthreads();
        }

        const unsigned sbr = pr ? sb1 : sb0;
        const float lg = s.logit[(rel >> 4) & 1][rel & 15][j];

        // 128 candidates: 32x broadcast LDS.128, 64x add.rn.f32x2, 8-acc tree
        float a0, a1, a2, a3, a4, a5, a6, a7;
        #pragma unroll
        for (int u = 0; u < 32; ++u) {
            unsigned long long p0, p1, c0, c1;
            asm volatile("ld.shared.v2.u64 {%0, %1}, [%2];"
                         : "=l"(p0), "=l"(p1) : "r"(sbr + 16 * u));
            asm("add.rn.f32x2 %0, %1, %2;" : "=l"(c0) : "l"(p0), "l"(t2[2 * u]));
            asm("add.rn.f32x2 %0, %1, %2;" : "=l"(c1) : "l"(p1), "l"(t2[2 * u + 1]));
            float x0, x1, x2, x3;
            asm("mov.b64 {%0, %1}, %2;" : "=f"(x0), "=f"(x1) : "l"(c0));
            asm("mov.b64 {%0, %1}, %2;" : "=f"(x2), "=f"(x3) : "l"(c1));
            if (u == 0)      { a0 = x0; a1 = x1; a2 = x2; a3 = x3; }
            else if (u == 1) { a4 = x0; a5 = x1; a6 = x2; a7 = x3; }
            else if (u & 1)  { a4 = fmaxf(a4, x0); a5 = fmaxf(a5, x1);
                               a6 = fmaxf(a6, x2); a7 = fmaxf(a7, x3); }
            else             { a0 = fmaxf(a0, x0); a1 = fmaxf(a1, x1);
                               a2 = fmaxf(a2, x2); a3 = fmaxf(a3, x3); }
        }
        float b0 = fmaxf(a0, a4), b1 = fmaxf(a1, a5);
        float b2 = fmaxf(a2, a6), b3 = fmaxf(a3, a7);
        float best = fmaxf(fmaxf(b0, b1), fmaxf(b2, b3)) + lg;

        s.spad[pr ^ 1][j] = best;
        g_state[((size_t)b * TT + t) * KK + j] = best;
        pr ^= 1;
        __syncthreads();
    }
    asm volatile("cp.async.wait_all;");

    // ---- last tag = argmax_j final state (warp 0, first-index tie-break) ----
    if (w == 0) {
        const float* st = s.spad[pr];
        unsigned u0 = f32_mono_u32(st[4 * lane + 0]);
        unsigned u1 = f32_mono_u32(st[4 * lane + 1]);
        unsigned u2 = f32_mono_u32(st[4 * lane + 2]);
        unsigned u3 = f32_mono_u32(st[4 * lane + 3]);
        unsigned lm = max(max(u0, u1), max(u2, u3));
        int li = (u0 == lm) ? 4 * lane
               : (u1 == lm) ? 4 * lane + 1
               : (u2 == lm) ? 4 * lane + 2
               :              4 * lane + 3;
        unsigned gm = __reduce_max_sync(0xffffffffu, lm);
        unsigned mk = __ballot_sync(0xffffffffu, lm == gm);
        int bi = __shfl_sync(0xffffffffu, li, __ffs(mk) - 1);
        if (lane == 0) s.lasttag = bi;
    }
    __syncthreads();
    const int lt = s.lasttag;

    // tail fill: tags[t] = last_tag for t >= len-1
    for (int t = len - 1 + tid; t < TT; t += NTHREADS) s.tags[t] = lt;

    // ================= backtrack: gmem-direct walk (warp 0 only) ============
    if (tid < 32) {
        int cur = lt;
        const float* gb = g_state + (size_t)b * TT * KK + 4 * lane;
        int hi = len - 2;
        if (hi >= 0) {
            float4 sv = *reinterpret_cast<const float4*>(gb + (size_t)hi * KK);
            float4 sv1;
            if (hi >= 1)
                sv1 = *reinterpret_cast<const float4*>(gb + (size_t)(hi - 1) * KK);
            for (int t = hi; t >= 0; --t) {
                float4 nv;                              // prefetch row t-2
                if (t >= 2)
                    nv = *reinterpret_cast<const float4*>(gb + (size_t)(t - 2) * KK);
                float4 tv = *reinterpret_cast<const float4*>(
                    &s.transC[cur * TC_STRIDE + 4 * lane]);
                unsigned u0 = f32_mono_u32(sv.x + tv.x);
                unsigned u1 = f32_mono_u32(sv.y + tv.y);
                unsigned u2 = f32_mono_u32(sv.z + tv.z);
                unsigned u3 = f32_mono_u32(sv.w + tv.w);
                unsigned lm = max(max(u0, u1), max(u2, u3));
                int li = (u0 == lm) ? 4 * lane
                       : (u1 == lm) ? 4 * lane + 1
                       : (u2 == lm) ? 4 * lane + 2
                       :              4 * lane + 3;
                unsigned gm = __reduce_max_sync(0xffffffffu, lm);
                unsigned mk = __ballot_sync(0xffffffffu, lm == gm);
                cur = __shfl_sync(0xffffffffu, li, __ffs(mk) - 1);
                if (lane == 0) s.tags[t] = cur;
                sv = sv1; sv1 = nv;
            }
        }
    }
    __syncthreads();

    // ================= one-hot output =================
    float* ob = out + (size_t)b * TT * KK;
    for (int it = 0; it < TT / 4; ++it) {
        int t = it * 4 + w;
        int tg = s.tags[t];
        float4 v;
        v.x = (tg == 4 * lane + 0) ? 1.0f : 0.0f;
        v.y = (tg == 4 * lane + 1) ? 1.0f : 0.0f;
        v.z = (tg == 4 * lane + 2) ? 1.0f : 0.0f;
        v.w = (tg == 4 * lane + 3) ? 1.0f : 0.0f;
        *reinterpret_cast<float4*>(ob + (size_t)t * KK + 4 * lane) = v;
    }
}

extern "C" void kernel_launch(void* const* d_in, const int* in_sizes, int n_in,
                              void* d_out, int out_size) {
    const float* logits = (const float*)d_in[0];
    const int*   lens   = (const int*)d_in[1];
    const float* trans  = (const float*)d_in[2];
    float*       out    = (float*)d_out;

    cudaFuncSetAttribute(crf_viterbi_kernel,
                         cudaFuncAttributeMaxDynamicSharedMemorySize,
                         (int)sizeof(SmemLayout));
    crf_viterbi_kernel<<<BB, NTHREADS, sizeof(SmemLayout)>>>(logits, lens, trans, out);
}

// round 13
// speedup vs baseline: 1.4961x; 1.4961x over previous
#include <cuda_runtime.h>
#include <cstdint>

// CRF Viterbi decode: B=128, T=1024, K=128. One CTA (128 threads) per batch.
// Forward (R6-proven, unchanged): thread per output column j; 32x broadcast
// LDS.128 of state, 64x add.rn.f32x2 vs transitions in 64 u64 regs, 8-acc
// FMNMX tree; post-logit state -> 64MB scratch; logits cp.async double-
// buffered; one __syncthreads per step.
// Backtrack (R13): R6's double-buffered cp.async 64-row staging (deep
// prefetch hides DRAM), but leaner serial chain: float FMNMX tree -> map
// ONLY the local max -> REDUX_max -> float-equality li -> REDUX_min.
// Exact first-index tie-break == jnp.argmax. One-hot f32 out.

#define BB 128
#define TT 1024
#define KK 128
#define TC_STRIDE 132
#define NTHREADS 128

__device__ float g_state[(size_t)BB * TT * KK];

struct __align__(16) SmemLayout {
    float transC[KK * TC_STRIDE];   // transC[j*132 + i] = T[i][j]
    float spad[2][KK];              // double-buffered state
    float logit[2][16][KK];         // double-buffered logit staging
    float block[2][64 * KK];        // double-buffered backtrack staging
    int   tags[TT];
    int   lasttag;
};

__device__ __forceinline__ unsigned smem_u32(const void* p) {
    return (unsigned)__cvta_generic_to_shared(p);
}
__device__ __forceinline__ void cp_async16(unsigned dst, const void* src) {
    asm volatile("cp.async.cg.shared.global [%0], [%1], 16;" :: "r"(dst), "l"(src));
}
__device__ __forceinline__ unsigned f32_mono_u32(float x) {
    unsigned b = __float_as_uint(x);
    return b ^ (unsigned)(((int)b >> 31) | 0x80000000);
}

__global__ void __launch_bounds__(NTHREADS, 1)
crf_viterbi_kernel(const float* __restrict__ logits,
                   const int*   __restrict__ lens,
                   const float* __restrict__ trans,
                   float*       __restrict__ out)
{
    extern __shared__ char smraw[];
    SmemLayout& s = *reinterpret_cast<SmemLayout*>(smraw);

    const int b    = blockIdx.x;
    const int tid  = threadIdx.x;
    const int w    = tid >> 5;         // 4 warps
    const int lane = tid & 31;
    const int j    = tid;              // output column owned by this thread
    const int len  = lens[b];

    // ---- transC staging (vectorized read, strided scalar STS; init-only) ----
    for (int idx = tid * 4; idx < KK * KK; idx += NTHREADS * 4) {
        float4 v = *reinterpret_cast<const float4*>(trans + idx);
        int i  = idx >> 7;
        int jj = idx & (KK - 1);
        s.transC[(jj + 0) * TC_STRIDE + i] = v.x;
        s.transC[(jj + 1) * TC_STRIDE + i] = v.y;
        s.transC[(jj + 2) * TC_STRIDE + i] = v.z;
        s.transC[(jj + 3) * TC_STRIDE + i] = v.w;
    }

    // ---- init state = logits[b, 0, :] ----
    {
        float v = logits[((size_t)b * TT) * KK + tid];
        s.spad[0][tid] = v;
        g_state[((size_t)b * TT) * KK + tid] = v;
    }

    // ---- prologue: stage logit rows 1..16 into buffer 0 ----
    {
        const float* base = logits + (size_t)b * TT * KK + lane * 4;
        #pragma unroll
        for (int k = 0; k < 4; ++k) {
            int ridx = w + 4 * k;          // row-in-epoch 0..15
            int r = 1 + ridx;  if (r > TT - 1) r = TT - 1;
            cp_async16(smem_u32(&s.logit[0][ridx][lane * 4]), base + (size_t)r * KK);
        }
        asm volatile("cp.async.commit_group;");
    }
    __syncthreads();

    // ---- this thread's 128 transitions (column j) from SMEM, 64 f32x2 ----
    unsigned long long t2[64];
    #pragma unroll
    for (int m = 0; m < 64; ++m) {
        float2 tp = *reinterpret_cast<const float2*>(
            &s.transC[j * TC_STRIDE + 2 * m]);
        asm("mov.b64 %0, {%1, %2};" : "=l"(t2[m]) : "f"(tp.x), "f"(tp.y));
    }

    const unsigned sb0 = smem_u32(&s.spad[0][0]);
    const unsigned sb1 = smem_u32(&s.spad[1][0]);
    int pr = 0;

    // ================= forward pass (value-only) =================
    for (int t = 1; t < len; ++t) {
        const int rel = t - 1;
        if ((rel & 15) == 0) {
            int g = rel >> 4;
            int base_row = 1 + (g + 1) * 16;
            int nb = (g + 1) & 1;
            const float* base = logits + (size_t)b * TT * KK + lane * 4;
            #pragma unroll
            for (int k = 0; k < 4; ++k) {
                int ridx = w + 4 * k;
                int r = base_row + ridx;  if (r > TT - 1) r = TT - 1;
                cp_async16(smem_u32(&s.logit[nb][ridx][lane * 4]),
                           base + (size_t)r * KK);
            }
            asm volatile("cp.async.commit_group;");
            asm volatile("cp.async.wait_group 1;");
            __syncthreads();
        }

        const unsigned sbr = pr ? sb1 : sb0;
        const float lg = s.logit[(rel >> 4) & 1][rel & 15][j];

        // 128 candidates: 32x broadcast LDS.128, 64x add.rn.f32x2, 8-acc tree
        float a0, a1, a2, a3, a4, a5, a6, a7;
        #pragma unroll
        for (int u = 0; u < 32; ++u) {
            unsigned long long p0, p1, c0, c1;
            asm volatile("ld.shared.v2.u64 {%0, %1}, [%2];"
                         : "=l"(p0), "=l"(p1) : "r"(sbr + 16 * u));
            asm("add.rn.f32x2 %0, %1, %2;" : "=l"(c0) : "l"(p0), "l"(t2[2 * u]));
            asm("add.rn.f32x2 %0, %1, %2;" : "=l"(c1) : "l"(p1), "l"(t2[2 * u + 1]));
            float x0, x1, x2, x3;
            asm("mov.b64 {%0, %1}, %2;" : "=f"(x0), "=f"(x1) : "l"(c0));
            asm("mov.b64 {%0, %1}, %2;" : "=f"(x2), "=f"(x3) : "l"(c1));
            if (u == 0)      { a0 = x0; a1 = x1; a2 = x2; a3 = x3; }
            else if (u == 1) { a4 = x0; a5 = x1; a6 = x2; a7 = x3; }
            else if (u & 1)  { a4 = fmaxf(a4, x0); a5 = fmaxf(a5, x1);
                               a6 = fmaxf(a6, x2); a7 = fmaxf(a7, x3); }
            else             { a0 = fmaxf(a0, x0); a1 = fmaxf(a1, x1);
                               a2 = fmaxf(a2, x2); a3 = fmaxf(a3, x3); }
        }
        float b0 = fmaxf(a0, a4), b1 = fmaxf(a1, a5);
        float b2 = fmaxf(a2, a6), b3 = fmaxf(a3, a7);
        float best = fmaxf(fmaxf(b0, b1), fmaxf(b2, b3)) + lg;

        s.spad[pr ^ 1][j] = best;
        g_state[((size_t)b * TT + t) * KK + j] = best;
        pr ^= 1;
        __syncthreads();
    }
    asm volatile("cp.async.wait_all;");

    // ---- last tag = argmax_j final state (warp 0, first-index tie-break) ----
    if (w == 0) {
        const float* st = s.spad[pr];
        float s0 = st[4 * lane + 0], s1 = st[4 * lane + 1];
        float s2 = st[4 * lane + 2], s3 = st[4 * lane + 3];
        float lm = fmaxf(fmaxf(s0, s1), fmaxf(s2, s3));
        unsigned lmu = f32_mono_u32(lm);
        unsigned gm = __reduce_max_sync(0xffffffffu, lmu);
        int li = (s0 == lm) ? 4 * lane
               : (s1 == lm) ? 4 * lane + 1
               : (s2 == lm) ? 4 * lane + 2
               :              4 * lane + 3;
        unsigned cand = (lmu == gm) ? (unsigned)li : 0xffffffffu;
        unsigned bi = __reduce_min_sync(0xffffffffu, cand);
        if (lane == 0) s.lasttag = (int)bi;
    }
    __syncthreads();
    const int lt = s.lasttag;

    // tail fill: tags[t] = last_tag for t >= len-1
    for (int t = len - 1 + tid; t < TT; t += NTHREADS) s.tags[t] = lt;

    // ================= backtrack (double-buffered staging + warp-0 walk) =====
    int cur = lt;
    int hi = len - 2;
    int bb2 = 0;
    if (hi >= 0) {
        {   // stage first block
            int lo2 = hi - 63; if (lo2 < 0) lo2 = 0;
            int n = (hi - lo2 + 1) * KK;
            const float* src = g_state + ((size_t)b * TT + lo2) * KK;
            for (int idx = tid * 4; idx < n; idx += NTHREADS * 4)
                cp_async16(smem_u32(&s.block[0][idx]), src + idx);
            asm volatile("cp.async.commit_group;");
        }
        while (hi >= 0) {
            int lo = hi - 63; if (lo < 0) lo = 0;
            int nhi = lo - 1;
            if (nhi >= 0) {
                int lo2 = nhi - 63; if (lo2 < 0) lo2 = 0;
                int n = (nhi - lo2 + 1) * KK;
                const float* src = g_state + ((size_t)b * TT + lo2) * KK;
                for (int idx = tid * 4; idx < n; idx += NTHREADS * 4)
                    cp_async16(smem_u32(&s.block[bb2 ^ 1][idx]), src + idx);
                asm volatile("cp.async.commit_group;");
                asm volatile("cp.async.wait_group 1;");
            } else {
                asm volatile("cp.async.wait_group 0;");
            }
            __syncthreads();

            if (tid < 32) {
                const float* blk = s.block[bb2];
                float4 sv = *reinterpret_cast<const float4*>(
                    &blk[(hi - lo) * KK + 4 * lane]);
                for (int t = hi; t >= lo; --t) {
                    float4 tv = *reinterpret_cast<const float4*>(
                        &s.transC[cur * TC_STRIDE + 4 * lane]);
                    float4 svn;
                    if (t > lo)
                        svn = *reinterpret_cast<const float4*>(
                            &blk[(t - 1 - lo) * KK + 4 * lane]);
                    // lean chain: float tree -> map 1 value -> 2x REDUX
                    float s0 = sv.x + tv.x, s1 = sv.y + tv.y;
                    float s2 = sv.z + tv.z, s3 = sv.w + tv.w;
                    float lm = fmaxf(fmaxf(s0, s1), fmaxf(s2, s3));
                    unsigned lmu = f32_mono_u32(lm);
                    unsigned gm = __reduce_max_sync(0xffffffffu, lmu);
                    int li = (s0 == lm) ? 4 * lane
                           : (s1 == lm) ? 4 * lane + 1
                           : (s2 == lm) ? 4 * lane + 2
                           :              4 * lane + 3;
                    unsigned cand = (lmu == gm) ? (unsigned)li : 0xffffffffu;
                    cur = (int)__reduce_min_sync(0xffffffffu, cand);
                    if (lane == 0) s.tags[t] = cur;
                    sv = svn;
                }
            }
            __syncthreads();
            hi = nhi;
            bb2 ^= 1;
        }
    }
    __syncthreads();  // covers len==1 path (tags tail-fill -> output)

    // ================= one-hot output =================
    float* ob = out + (size_t)b * TT * KK;
    for (int it = 0; it < TT / 4; ++it) {
        int t = it * 4 + w;
        int tg = s.tags[t];
        float4 v;
        v.x = (tg == 4 * lane + 0) ? 1.0f : 0.0f;
        v.y = (tg == 4 * lane + 1) ? 1.0f : 0.0f;
        v.z = (tg == 4 * lane + 2) ? 1.0f : 0.0f;
        v.w = (tg == 4 * lane + 3) ? 1.0f : 0.0f;
        *reinterpret_cast<float4*>(ob + (size_t)t * KK + 4 * lane) = v;
    }
}

extern "C" void kernel_launch(void* const* d_in, const int* in_sizes, int n_in,
                              void* d_out, int out_size) {
    const float* logits = (const float*)d_in[0];
    const int*   lens   = (const int*)d_in[1];
    const float* trans  = (const float*)d_in[2];
    float*       out    = (float*)d_out;

    cudaFuncSetAttribute(crf_viterbi_kernel,
                         cudaFuncAttributeMaxDynamicSharedMemorySize,
                         (int)sizeof(SmemLayout));
    crf_viterbi_kernel<<<BB, NTHREADS, sizeof(SmemLayout)>>>(logits, lens, trans, out);
}

// round 14
// speedup vs baseline: 1.5224x; 1.0175x over previous
#include <cuda_runtime.h>
#include <cstdint>

// CRF Viterbi decode: B=128, T=1024, K=128. One CTA (128 threads) per batch.
// Forward (R6/R13 math, R14 pipeline): thread per column j; 32x broadcast
// LDS.128 of state, 64x add.rn.f32x2 vs transitions in 64 u64 regs, 8-acc
// FMNMX tree. Logit epochs: issue at first step of each epoch (race-free),
// wait_group 0 folded into the last step of the prior epoch => NO extra
// epoch barrier. State -> 64MB scratch (one STG/step).
// Backtrack (R14, warp-specialized): warp 0 walks block k (R13 lean chain:
// float FMNMX tree -> map 1 value -> REDUX_max -> REDUX_min, exact
// first-index tie-break == jnp.argmax) while warps 1-3 stage block k+1 via
// cp.async AND write the one-hot rows of block k-1. Rows [len-1,TT) one-hot
// written up-front. One-hot tail phase eliminated from the critical path.

#define BB 128
#define TT 1024
#define KK 128
#define TC_STRIDE 132
#define NTHREADS 128

__device__ float g_state[(size_t)BB * TT * KK];

struct __align__(16) SmemLayout {
    float transC[KK * TC_STRIDE];   // transC[j*132 + i] = T[i][j]
    float spad[2][KK];              // double-buffered state
    float logit[2][16][KK];         // double-buffered logit staging
    float block[2][64 * KK];        // double-buffered backtrack staging
    int   tags[TT];
    int   lasttag;
};

__device__ __forceinline__ unsigned smem_u32(const void* p) {
    return (unsigned)__cvta_generic_to_shared(p);
}
__device__ __forceinline__ void cp_async16(unsigned dst, const void* src) {
    asm volatile("cp.async.cg.shared.global [%0], [%1], 16;" :: "r"(dst), "l"(src));
}
__device__ __forceinline__ unsigned f32_mono_u32(float x) {
    unsigned b = __float_as_uint(x);
    return b ^ (unsigned)(((int)b >> 31) | 0x80000000);
}

__global__ void __launch_bounds__(NTHREADS, 1)
crf_viterbi_kernel(const float* __restrict__ logits,
                   const int*   __restrict__ lens,
                   const float* __restrict__ trans,
                   float*       __restrict__ out)
{
    extern __shared__ char smraw[];
    SmemLayout& s = *reinterpret_cast<SmemLayout*>(smraw);

    const int b    = blockIdx.x;
    const int tid  = threadIdx.x;
    const int w    = tid >> 5;         // 4 warps
    const int lane = tid & 31;
    const int j    = tid;              // output column owned by this thread
    const int len  = lens[b];

    // ---- transC staging (vectorized read, strided scalar STS; init-only) ----
    for (int idx = tid * 4; idx < KK * KK; idx += NTHREADS * 4) {
        float4 v = *reinterpret_cast<const float4*>(trans + idx);
        int i  = idx >> 7;
        int jj = idx & (KK - 1);
        s.transC[(jj + 0) * TC_STRIDE + i] = v.x;
        s.transC[(jj + 1) * TC_STRIDE + i] = v.y;
        s.transC[(jj + 2) * TC_STRIDE + i] = v.z;
        s.transC[(jj + 3) * TC_STRIDE + i] = v.w;
    }

    // ---- init state = logits[b, 0, :] ----
    {
        float v = logits[((size_t)b * TT) * KK + tid];
        s.spad[0][tid] = v;
        g_state[((size_t)b * TT) * KK + tid] = v;
    }

    // ---- prologue: stage logit epoch 0 (rows 1..16) into buffer 0 ----
    {
        const float* base = logits + (size_t)b * TT * KK + lane * 4;
        #pragma unroll
        for (int k = 0; k < 4; ++k) {
            int ridx = w + 4 * k;          // row-in-epoch 0..15
            int r = 1 + ridx;  if (r > TT - 1) r = TT - 1;
            cp_async16(smem_u32(&s.logit[0][ridx][lane * 4]), base + (size_t)r * KK);
        }
        asm volatile("cp.async.commit_group;");
    }
    __syncthreads();   // transC visible

    // ---- this thread's 128 transitions (column j) from SMEM, 64 f32x2 ----
    unsigned long long t2[64];
    #pragma unroll
    for (int m = 0; m < 64; ++m) {
        float2 tp = *reinterpret_cast<const float2*>(
            &s.transC[j * TC_STRIDE + 2 * m]);
        asm("mov.b64 %0, {%1, %2};" : "=l"(t2[m]) : "f"(tp.x), "f"(tp.y));
    }
    asm volatile("cp.async.wait_group 0;");
    __syncthreads();   // epoch 0 data visible

    const unsigned sb0 = smem_u32(&s.spad[0][0]);
    const unsigned sb1 = smem_u32(&s.spad[1][0]);
    int pr = 0;

    // ================= forward pass (value-only) =================
    for (int t = 1; t < len; ++t) {
        const int rel = t - 1;
        // first step of epoch E: issue staging for epoch E+1 (no wait here).
        // Buffer (E+1)&1 was last read in epoch E-1 (done, barrier passed).
        if ((rel & 15) == 0) {
            int Enext = (rel >> 4) + 1;
            int base_row = 1 + Enext * 16;
            int nb = Enext & 1;
            const float* base = logits + (size_t)b * TT * KK + lane * 4;
            #pragma unroll
            for (int k = 0; k < 4; ++k) {
                int ridx = w + 4 * k;
                int r = base_row + ridx;  if (r > TT - 1) r = TT - 1;
                cp_async16(smem_u32(&s.logit[nb][ridx][lane * 4]),
                           base + (size_t)r * KK);
            }
            asm volatile("cp.async.commit_group;");
        }

        const unsigned sbr = pr ? sb1 : sb0;
        const float lg = s.logit[(rel >> 4) & 1][rel & 15][j];

        // 128 candidates: 32x broadcast LDS.128, 64x add.rn.f32x2, 8-acc tree
        float a0, a1, a2, a3, a4, a5, a6, a7;
        #pragma unroll
        for (int u = 0; u < 32; ++u) {
            unsigned long long p0, p1, c0, c1;
            asm volatile("ld.shared.v2.u64 {%0, %1}, [%2];"
                         : "=l"(p0), "=l"(p1) : "r"(sbr + 16 * u));
            asm("add.rn.f32x2 %0, %1, %2;" : "=l"(c0) : "l"(p0), "l"(t2[2 * u]));
            asm("add.rn.f32x2 %0, %1, %2;" : "=l"(c1) : "l"(p1), "l"(t2[2 * u + 1]));
            float x0, x1, x2, x3;
            asm("mov.b64 {%0, %1}, %2;" : "=f"(x0), "=f"(x1) : "l"(c0));
            asm("mov.b64 {%0, %1}, %2;" : "=f"(x2), "=f"(x3) : "l"(c1));
            if (u == 0)      { a0 = x0; a1 = x1; a2 = x2; a3 = x3; }
            else if (u == 1) { a4 = x0; a5 = x1; a6 = x2; a7 = x3; }
            else if (u & 1)  { a4 = fmaxf(a4, x0); a5 = fmaxf(a5, x1);
                               a6 = fmaxf(a6, x2); a7 = fmaxf(a7, x3); }
            else             { a0 = fmaxf(a0, x0); a1 = fmaxf(a1, x1);
                               a2 = fmaxf(a2, x2); a3 = fmaxf(a3, x3); }
        }
        float b0 = fmaxf(a0, a4), b1 = fmaxf(a1, a5);
        float b2 = fmaxf(a2, a6), b3 = fmaxf(a3, a7);
        float best = fmaxf(fmaxf(b0, b1), fmaxf(b2, b3)) + lg;

        s.spad[pr ^ 1][j] = best;
        g_state[((size_t)b * TT + t) * KK + j] = best;
        pr ^= 1;
        // last step of epoch E: ensure epoch E+1's data (in flight ~16 steps)
        // is complete before the barrier publishes it for the next step.
        if ((rel & 15) == 15)
            asm volatile("cp.async.wait_group 0;");
        __syncthreads();
    }
    asm volatile("cp.async.wait_all;");

    // ---- last tag = argmax_j final state (warp 0, first-index tie-break) ----
    if (w == 0) {
        const float* st = s.spad[pr];
        float s0 = st[4 * lane + 0], s1 = st[4 * lane + 1];
        float s2 = st[4 * lane + 2], s3 = st[4 * lane + 3];
        float lm = fmaxf(fmaxf(s0, s1), fmaxf(s2, s3));
        unsigned lmu = f32_mono_u32(lm);
        unsigned gm = __reduce_max_sync(0xffffffffu, lmu);
        int li = (s0 == lm) ? 4 * lane
               : (s1 == lm) ? 4 * lane + 1
               : (s2 == lm) ? 4 * lane + 2
               :              4 * lane + 3;
        unsigned cand = (lmu == gm) ? (unsigned)li : 0xffffffffu;
        unsigned bi = __reduce_min_sync(0xffffffffu, cand);
        if (lane == 0) s.lasttag = (int)bi;
    }
    __syncthreads();
    const int lt = s.lasttag;

    float* ob = out + (size_t)b * TT * KK;
    int hi = len - 2;
    int bb2 = 0;

    // ---- stage backtrack block 0 (all threads) ----
    if (hi >= 0) {
        int lo2 = hi - 63; if (lo2 < 0) lo2 = 0;
        int n = (hi - lo2 + 1) * KK;
        const float* src = g_state + ((size_t)b * TT + lo2) * KK;
        for (int idx = tid * 4; idx < n; idx += NTHREADS * 4)
            cp_async16(smem_u32(&s.block[0][idx]), src + idx);
        asm volatile("cp.async.commit_group;");
    }

    // ---- up-front one-hot for rows [len-1, TT) (overlaps staging flight) ----
    {
        float4 v;
        v.x = (lt == 4 * lane + 0) ? 1.0f : 0.0f;
        v.y = (lt == 4 * lane + 1) ? 1.0f : 0.0f;
        v.z = (lt == 4 * lane + 2) ? 1.0f : 0.0f;
        v.w = (lt == 4 * lane + 3) ? 1.0f : 0.0f;
        for (int t = len - 1 + w; t < TT; t += 4)
            *reinterpret_cast<float4*>(ob + (size_t)t * KK + 4 * lane) = v;
    }

    // ================= backtrack: warp-specialized blocks ===================
    if (hi >= 0) {
        asm volatile("cp.async.wait_group 0;");
        __syncthreads();
        int cur = lt;
        int plo = -1, phi = -1;
        while (hi >= 0) {
            int lo = hi - 63; if (lo < 0) lo = 0;
            int nhi = lo - 1;
            if (tid < 32) {
                // ---- warp 0: serial walk of block [lo..hi] ----
                const float* blk = s.block[bb2];
                float4 sv = *reinterpret_cast<const float4*>(
                    &blk[(hi - lo) * KK + 4 * lane]);
                for (int t = hi; t >= lo; --t) {
                    float4 tv = *reinterpret_cast<const float4*>(
                        &s.transC[cur * TC_STRIDE + 4 * lane]);
                    float4 svn;
                    if (t > lo)
                        svn = *reinterpret_cast<const float4*>(
                            &blk[(t - 1 - lo) * KK + 4 * lane]);
                    float s0 = sv.x + tv.x, s1 = sv.y + tv.y;
                    float s2 = sv.z + tv.z, s3 = sv.w + tv.w;
                    float lm = fmaxf(fmaxf(s0, s1), fmaxf(s2, s3));
                    unsigned lmu = f32_mono_u32(lm);
                    unsigned gm = __reduce_max_sync(0xffffffffu, lmu);
                    int li = (s0 == lm) ? 4 * lane
                           : (s1 == lm) ? 4 * lane + 1
                           : (s2 == lm) ? 4 * lane + 2
                           :              4 * lane + 3;
                    unsigned cand = (lmu == gm) ? (unsigned)li : 0xffffffffu;
                    cur = (int)__reduce_min_sync(0xffffffffu, cand);
                    if (lane == 0) s.tags[t] = cur;
                    sv = svn;
                }
            } else {
                // ---- warps 1-3: stage next block + one-hot prev block ----
                if (nhi >= 0) {
                    int lo2 = nhi - 63; if (lo2 < 0) lo2 = 0;
                    int n = (nhi - lo2 + 1) * KK;
                    const float* src = g_state + ((size_t)b * TT + lo2) * KK;
                    for (int idx = (tid - 32) * 4; idx < n; idx += 96 * 4)
                        cp_async16(smem_u32(&s.block[bb2 ^ 1][idx]), src + idx);
                    asm volatile("cp.async.commit_group;");
                }
                if (phi >= 0) {
                    for (int t = plo + (w - 1); t <= phi; t += 3) {
                        int tg = s.tags[t];
                        float4 v;
                        v.x = (tg == 4 * lane + 0) ? 1.0f : 0.0f;
                        v.y = (tg == 4 * lane + 1) ? 1.0f : 0.0f;
                        v.z = (tg == 4 * lane + 2) ? 1.0f : 0.0f;
                        v.w = (tg == 4 * lane + 3) ? 1.0f : 0.0f;
                        *reinterpret_cast<float4*>(
                            ob + (size_t)t * KK + 4 * lane) = v;
                    }
                }
                if (nhi >= 0)
                    asm volatile("cp.async.wait_group 0;");
            }
            __syncthreads();
            plo = lo; phi = hi;
            hi = nhi; bb2 ^= 1;
        }
        // ---- final block one-hot (all threads) ----
        for (int t = plo + w; t <= phi; t += 4) {
            int tg = s.tags[t];
            float4 v;
            v.x = (tg == 4 * lane + 0) ? 1.0f : 0.0f;
            v.y = (tg == 4 * lane + 1) ? 1.0f : 0.0f;
            v.z = (tg == 4 * lane + 2) ? 1.0f : 0.0f;
            v.w = (tg == 4 * lane + 3) ? 1.0f : 0.0f;
            *reinterpret_cast<float4*>(ob + (size_t)t * KK + 4 * lane) = v;
        }
    }
}

extern "C" void kernel_launch(void* const* d_in, const int* in_sizes, int n_in,
                              void* d_out, int out_size) {
    const float* logits = (const float*)d_in[0];
    const int*   lens   = (const int*)d_in[1];
    const float* trans  = (const float*)d_in[2];
    float*       out    = (float*)d_out;

    cudaFuncSetAttribute(crf_viterbi_kernel,
                         cudaFuncAttributeMaxDynamicSharedMemorySize,
                         (int)sizeof(SmemLayout));
    crf_viterbi_kernel<<<BB, NTHREADS, sizeof(SmemLayout)>>>(logits, lens, trans, out);
}